// round 10
// baseline (speedup 1.0000x reference)
#include <cuda_runtime.h>

#define SEQ   4096
#define HD    64
#define NL    64
#define NBH   48
#define NSP   16
#define CHUNK 256
#define PT    65
#define TPT   68
#define INVSC 0.35355339059327373f

typedef unsigned long long u64;

// ---------------- static scratch (no allocation) ----------------
__device__ float g_Qland[NBH*NL*HD];
__device__ float g_Kland[NBH*NL*HD];
__device__ float g_K2  [NBH*NL*NL];
__device__ float g_pinv[NBH*NL*NL];
__device__ float g_Wm  [NBH*NL*HD];
__device__ float g_Fp  [NBH*NSP*NL*HD];
__device__ float g_mp  [NBH*NSP*NL];
__device__ float g_sp  [NBH*NSP*NL];
__device__ float g_norms[2*NBH];

// ---------------- f32x2 packed helpers ----------------
__device__ __forceinline__ u64 pk2(float lo, float hi) {
    u64 r; asm("mov.b64 %0,{%1,%2};" : "=l"(r) : "f"(lo), "f"(hi)); return r;
}
__device__ __forceinline__ void upk2(u64 v, float& lo, float& hi) {
    asm("mov.b64 {%0,%1},%2;" : "=f"(lo), "=f"(hi) : "l"(v));
}
__device__ __forceinline__ u64 fma2(u64 a, u64 b, u64 c) {
    u64 d; asm("fma.rn.f32x2 %0,%1,%2,%3;" : "=l"(d) : "l"(a), "l"(b), "l"(c)); return d;
}
__device__ __forceinline__ u64 mul2(u64 a, u64 b) {
    u64 d; asm("mul.rn.f32x2 %0,%1,%2;" : "=l"(d) : "l"(a), "l"(b)); return d;
}

// ---------------- warp helpers ----------------
__device__ __forceinline__ float warpMax(float v) {
    #pragma unroll
    for (int o = 16; o > 0; o >>= 1) v = fmaxf(v, __shfl_xor_sync(0xffffffffu, v, o));
    return v;
}
__device__ __forceinline__ float warpSum(float v) {
    #pragma unroll
    for (int o = 16; o > 0; o >>= 1) v += __shfl_xor_sync(0xffffffffu, v, o);
    return v;
}

// C = alpha * A @ B, 64x64 pitch-64, 256 threads (scalar version for kInv/kCombine)
__device__ __forceinline__ void mm64(const float* __restrict__ A,
                                     const float* __restrict__ B,
                                     float* __restrict__ C,
                                     int tid, float alpha)
{
    const int w = tid >> 5, lane = tid & 31;
    const int r0 = w * 8, cc = lane * 2;
    float ax[8], ay[8];
    #pragma unroll
    for (int r = 0; r < 8; r++) { ax[r] = 0.f; ay[r] = 0.f; }
    #pragma unroll
    for (int k = 0; k < 64; k += 4) {
        float2 b0 = *(const float2*)(B + (k+0)*64 + cc);
        float2 b1 = *(const float2*)(B + (k+1)*64 + cc);
        float2 b2 = *(const float2*)(B + (k+2)*64 + cc);
        float2 b3 = *(const float2*)(B + (k+3)*64 + cc);
        #pragma unroll
        for (int r = 0; r < 8; r++) {
            float4 a = *(const float4*)(A + (r0+r)*64 + k);
            ax[r] += a.x*b0.x + a.y*b1.x + a.z*b2.x + a.w*b3.x;
            ay[r] += a.x*b0.y + a.y*b1.y + a.z*b2.y + a.w*b3.y;
        }
    }
    #pragma unroll
    for (int r = 0; r < 8; r++)
        *(float2*)(C + (r0+r)*64 + cc) = make_float2(alpha*ax[r], alpha*ay[r]);
}

// ---------------- phase 1: landmarks + kernel_2 + norms ----------------
__global__ void kLand(const float* __restrict__ Q, const float* __restrict__ K)
{
    extern __shared__ float sm[];
    float* sQl  = sm;
    float* sKl  = sQl + NL*HD;
    float* sL   = sKl + NL*PT;
    float* sCol = sL  + NL*NL;
    float* sRed = sCol + 8*64;

    const int bh = blockIdx.x, tid = threadIdx.x;
    const float* Qb = Q + (size_t)bh*SEQ*HD;
    const float* Kb = K + (size_t)bh*SEQ*HD;
    const float cs = INVSC * (1.0f/64.0f);

    // pooling with float4 loads: 8x fewer LDG, much better MLP
    for (int e4 = tid; e4 < NL*HD/4; e4 += 256) {
        int l = e4 >> 4, d4 = (e4 & 15) << 2;
        const float4* qp = (const float4*)(Qb + (size_t)(l*64)*HD + d4);
        const float4* kp = (const float4*)(Kb + (size_t)(l*64)*HD + d4);
        float4 aq = make_float4(0.f,0.f,0.f,0.f);
        float4 ak = make_float4(0.f,0.f,0.f,0.f);
        #pragma unroll 8
        for (int r = 0; r < 64; r++) {
            float4 q = qp[r*16];
            float4 k2 = kp[r*16];
            aq.x += q.x; aq.y += q.y; aq.z += q.z; aq.w += q.w;
            ak.x += k2.x; ak.y += k2.y; ak.z += k2.z; ak.w += k2.w;
        }
        aq.x *= cs; aq.y *= cs; aq.z *= cs; aq.w *= cs;
        ak.x *= cs; ak.y *= cs; ak.z *= cs; ak.w *= cs;
        *(float4*)(sQl + l*64 + d4) = aq;
        sKl[l*PT + d4+0] = ak.x; sKl[l*PT + d4+1] = ak.y;
        sKl[l*PT + d4+2] = ak.z; sKl[l*PT + d4+3] = ak.w;
        *(float4*)(g_Qland + bh*NL*HD + l*64 + d4) = aq;
        *(float4*)(g_Kland + bh*NL*HD + l*64 + d4) = ak;
    }
    __syncthreads();

    const int w = tid >> 5, lane = tid & 31;
    const int r0 = w * 8;

    float px[8], py[8];
    #pragma unroll
    for (int r = 0; r < 8; r++) { px[r] = 0.f; py[r] = 0.f; }
    #pragma unroll
    for (int k = 0; k < 64; k += 4) {
        const float* bp0 = sKl + lane*PT + k;
        const float* bp1 = sKl + (lane+32)*PT + k;
        float b00 = bp0[0], b01 = bp0[1], b02 = bp0[2], b03 = bp0[3];
        float b10 = bp1[0], b11 = bp1[1], b12 = bp1[2], b13 = bp1[3];
        #pragma unroll
        for (int r = 0; r < 8; r++) {
            float4 a = *(const float4*)(sQl + (r0+r)*64 + k);
            px[r] += a.x*b00 + a.y*b01 + a.z*b02 + a.w*b03;
            py[r] += a.x*b10 + a.y*b11 + a.z*b12 + a.w*b13;
        }
    }

    float cs0 = 0.f, cs1 = 0.f;
    #pragma unroll
    for (int r = 0; r < 8; r++) {
        const int i = r0 + r;
        float mx = warpMax(fmaxf(px[r], py[r]));
        float p0 = __expf(px[r] - mx), p1 = __expf(py[r] - mx);
        float s = warpSum(p0 + p1);
        float inv = 1.f / s;
        p0 *= inv; p1 *= inv;
        sL[i*64 + lane] = p0;
        sL[i*64 + lane + 32] = p1;
        cs0 += p0; cs1 += p1;
        float rs = warpSum(p0 + p1);
        if (lane == 0) sRed[i] = rs;
    }
    sCol[w*64 + lane] = cs0;
    sCol[w*64 + lane + 32] = cs1;
    __syncthreads();

    for (int e = tid; e < NL*NL; e += 256) g_K2[bh*NL*NL + e] = sL[e];
    if (tid < 64) {
        float t = 0.f;
        #pragma unroll
        for (int ww = 0; ww < 8; ww++) t += sCol[ww*64 + tid];
        sRed[64 + tid] = t;
    }
    __syncthreads();
    if (tid == 0) {
        float rm = 0.f, cm = 0.f;
        for (int t = 0; t < 64; t++) {
            rm = fmaxf(rm, sRed[t]);
            cm = fmaxf(cm, sRed[64 + t]);
        }
        g_norms[bh] = rm;
        g_norms[NBH + bh] = cm;
    }
}

// ---------------- phase 2: Newton-Schulz pseudo-inverse ----------------
__global__ void kInv()
{
    extern __shared__ float sm[];
    float* bK = sm;
    float* bA = sm + 4096;
    float* bT = sm + 2*4096;
    float* bV = sm + 3*4096;
    float* bU = sm + 4*4096;
    const int bh = blockIdx.x, tid = threadIdx.x;

    for (int e = tid; e < 4096; e += 256) bK[e] = g_K2[bh*4096 + e];
    __syncthreads();
    float rm = 0.f, cm = 0.f;
    #pragma unroll
    for (int i = 0; i < NBH; i++) {
        rm = fmaxf(rm, g_norms[i]);
        cm = fmaxf(cm, g_norms[NBH + i]);
    }
    const float sc = 1.f / (rm * cm);
    for (int e = tid; e < 4096; e += 256) {
        int i = e >> 6, j = e & 63;
        bV[e] = sc * bK[j*64 + i];
    }
    __syncthreads();

    for (int it = 0; it < 6; it++) {
        mm64(bK, bV, bA, tid, 1.f); __syncthreads();
        for (int e = tid; e < 4096; e += 256)
            bT[e] = (((e>>6) == (e&63)) ? 7.f : 0.f) - bA[e];
        __syncthreads();
        mm64(bA, bT, bU, tid, 1.f); __syncthreads();
        for (int e = tid; e < 4096; e += 256)
            bT[e] = (((e>>6) == (e&63)) ? 15.f : 0.f) - bU[e];
        __syncthreads();
        mm64(bA, bT, bU, tid, 1.f); __syncthreads();
        for (int e = tid; e < 4096; e += 256)
            bT[e] = (((e>>6) == (e&63)) ? 13.f : 0.f) - bU[e];
        __syncthreads();
        mm64(bV, bT, bU, tid, 0.25f); __syncthreads();
        float* t = bV; bV = bU; bU = t;
    }
    for (int e = tid; e < 4096; e += 256) g_pinv[bh*4096 + e] = bV[e];
}

// ---------------- phase 4: kernel_3 @ V with split online softmax (f32x2) ----------------
// smem: sQlT[64*TPT] sK[64*PT] sV[64*64] sPT[64*TPT]
__global__ void __launch_bounds__(256, 3)
kChunk(const float* __restrict__ K, const float* __restrict__ V)
{
    extern __shared__ float sm[];
    float* sQlT = sm;
    float* sK   = sQlT + NL*TPT;
    float* sV   = sK   + NL*PT;
    float* sPT  = sV   + NL*HD;

    const int bh = blockIdx.y, sp = blockIdx.x, tid = threadIdx.x;
    const int w = tid >> 5, lane = tid & 31;
    const int r0 = w * 8, cc = lane * 2;

    // transposed landmark-Q tile (coalesced gmem read; 4-way smem write conflict, once)
    for (int e = tid; e < 4096; e += 256) {
        int i = e >> 6, d = e & 63;
        sQlT[d*TPT + i] = g_Qland[bh*4096 + e];
    }

    u64 fxp[4], fyp[4];
    float mrun[8], srun[8];
    #pragma unroll
    for (int p = 0; p < 4; p++) { fxp[p] = 0ull; fyp[p] = 0ull; }
    #pragma unroll
    for (int r = 0; r < 8; r++) { mrun[r] = -1e30f; srun[r] = 0.f; }

    for (int t = 0; t < 4; t++) {
        __syncthreads();
        const size_t rowBase = (size_t)bh*SEQ + sp*CHUNK + t*64;
        const float* Kb = K + rowBase*HD;
        const float* Vb = V + rowBase*HD;
        for (int e = tid; e < NL*HD; e += 256) {
            int j = e >> 6, d = e & 63;
            sK[j*PT + d] = Kb[e] * INVSC;
            sV[e] = Vb[e];
        }
        __syncthreads();

        // logits: row-pair packed f32x2
        u64 pxp[4], pyp[4];
        #pragma unroll
        for (int p = 0; p < 4; p++) { pxp[p] = 0ull; pyp[p] = 0ull; }
        const float* cK0 = sK + lane*PT;
        const float* cK1 = sK + (lane+32)*PT;
        #pragma unroll 8
        for (int d = 0; d < 64; d++) {
            ulonglong2 a0 = *(const ulonglong2*)(sQlT + d*TPT + r0);
            ulonglong2 a1 = *(const ulonglong2*)(sQlT + d*TPT + r0 + 4);
            float b0 = cK0[d], b1 = cK1[d];
            u64 bb0 = pk2(b0, b0), bb1 = pk2(b1, b1);
            pxp[0] = fma2(a0.x, bb0, pxp[0]); pxp[1] = fma2(a0.y, bb0, pxp[1]);
            pxp[2] = fma2(a1.x, bb0, pxp[2]); pxp[3] = fma2(a1.y, bb0, pxp[3]);
            pyp[0] = fma2(a0.x, bb1, pyp[0]); pyp[1] = fma2(a0.y, bb1, pyp[1]);
            pyp[2] = fma2(a1.x, bb1, pyp[2]); pyp[3] = fma2(a1.y, bb1, pyp[3]);
        }
        float px[8], py[8];
        #pragma unroll
        for (int p = 0; p < 4; p++) {
            upk2(pxp[p], px[2*p], px[2*p+1]);
            upk2(pyp[p], py[2*p], py[2*p+1]);
        }

        float al[8];
        #pragma unroll
        for (int r = 0; r < 8; r++) {
            const int i = r0 + r;
            float tmax = warpMax(fmaxf(px[r], py[r]));
            float nm = fmaxf(mrun[r], tmax);
            al[r] = __expf(mrun[r] - nm);
            float p0 = __expf(px[r] - nm), p1 = __expf(py[r] - nm);
            srun[r] = srun[r]*al[r] + warpSum(p0 + p1);
            mrun[r] = nm;
            sPT[lane*TPT + i] = p0;
            sPT[(lane+32)*TPT + i] = p1;
        }
        __syncwarp();   // P rows are warp-private in sPT -> no block barrier needed

        #pragma unroll
        for (int p = 0; p < 4; p++) {
            u64 alp = pk2(al[2*p], al[2*p+1]);
            fxp[p] = mul2(fxp[p], alp);
            fyp[p] = mul2(fyp[p], alp);
        }

        // PV: row-pair packed f32x2
        #pragma unroll 8
        for (int j = 0; j < 64; j++) {
            ulonglong2 a0 = *(const ulonglong2*)(sPT + j*TPT + r0);
            ulonglong2 a1 = *(const ulonglong2*)(sPT + j*TPT + r0 + 4);
            float2 v = *(const float2*)(sV + j*64 + cc);
            u64 vx = pk2(v.x, v.x), vy = pk2(v.y, v.y);
            fxp[0] = fma2(a0.x, vx, fxp[0]); fxp[1] = fma2(a0.y, vx, fxp[1]);
            fxp[2] = fma2(a1.x, vx, fxp[2]); fxp[3] = fma2(a1.y, vx, fxp[3]);
            fyp[0] = fma2(a0.x, vy, fyp[0]); fyp[1] = fma2(a0.y, vy, fyp[1]);
            fyp[2] = fma2(a1.x, vy, fyp[2]); fyp[3] = fma2(a1.y, vy, fyp[3]);
        }
    }

    const size_t base = (size_t)bh*NSP + sp;
    #pragma unroll
    for (int r = 0; r < 8; r++) {
        if (lane == 0) {
            g_mp[base*64 + r0 + r] = mrun[r];
            g_sp[base*64 + r0 + r] = srun[r];
        }
    }
    #pragma unroll
    for (int p = 0; p < 4; p++) {
        float f0x, f1x, f0y, f1y;
        upk2(fxp[p], f0x, f1x);
        upk2(fyp[p], f0y, f1y);
        const int i0 = r0 + 2*p;
        *(float2*)(g_Fp + base*4096 + i0*64 + cc)     = make_float2(f0x, f0y);
        *(float2*)(g_Fp + base*4096 + (i0+1)*64 + cc) = make_float2(f1x, f1y);
    }
}

// ---------------- phase 5: combine split partials + W = pinv @ F ----------------
__global__ void kCombine()
{
    extern __shared__ float sm[];
    float* sMs  = sm;
    float* sSs  = sMs + NSP*NL;
    float* sWt  = sSs + NSP*NL;
    float* sInv = sWt + NSP*NL;
    float* sF   = sInv + 64;
    float* sPinv = sF + 4096;

    const int bh = blockIdx.x, tid = threadIdx.x;
    for (int e = tid; e < NSP*NL; e += 256) {
        sMs[e] = g_mp[bh*NSP*NL + e];
        sSs[e] = g_sp[bh*NSP*NL + e];
    }
    __syncthreads();
    if (tid < 64) {
        float M = -1e30f;
        #pragma unroll
        for (int sp = 0; sp < NSP; sp++) M = fmaxf(M, sMs[sp*64 + tid]);
        float S = 0.f;
        #pragma unroll
        for (int sp = 0; sp < NSP; sp++) {
            float wgt = __expf(sMs[sp*64 + tid] - M);
            sWt[sp*64 + tid] = wgt;
            S += wgt * sSs[sp*64 + tid];
        }
        sInv[tid] = 1.f / S;
    }
    __syncthreads();
    // float4 partial reduction over the 16 splits (LDG.128, high MLP)
    for (int e4 = tid; e4 < 1024; e4 += 256) {
        const int i = e4 >> 4;
        float4 acc = make_float4(0.f,0.f,0.f,0.f);
        #pragma unroll
        for (int sp = 0; sp < NSP; sp++) {
            float4 v = *(const float4*)(g_Fp + ((size_t)bh*NSP + sp)*4096 + e4*4);
            float wgt = sWt[sp*64 + i];
            acc.x += wgt*v.x; acc.y += wgt*v.y; acc.z += wgt*v.z; acc.w += wgt*v.w;
        }
        float inv = sInv[i];
        *(float4*)(sF + e4*4) = make_float4(acc.x*inv, acc.y*inv, acc.z*inv, acc.w*inv);
    }
    for (int e4 = tid; e4 < 1024; e4 += 256)
        *(float4*)(sPinv + e4*4) = *(const float4*)(g_pinv + bh*4096 + e4*4);
    __syncthreads();
    mm64(sPinv, sF, g_Wm + bh*4096, tid, 1.f);
}

// ---------------- phase 6: out = softmax(Q @ Kland^T) @ W (f32x2) ----------------
// smem: sQT[64*TPT] sKl[64*PT] sPT[64*TPT] sW[64*64]
__global__ void __launch_bounds__(256, 3)
kFinal(const float* __restrict__ Q, float* __restrict__ out)
{
    extern __shared__ float sm[];
    float* sQT = sm;
    float* sKl = sQT + NL*TPT;
    float* sPT = sKl + NL*PT;
    float* sW  = sPT + NL*TPT;

    const int bh = blockIdx.y, tile = blockIdx.x, tid = threadIdx.x;
    const int w = tid >> 5, lane = tid & 31;
    const int r0 = w * 8, cc = lane * 2;

    const float* Qb = Q + ((size_t)bh*SEQ + tile*64)*HD;
    for (int e = tid; e < 4096; e += 256) {
        int i = e >> 6, d = e & 63;
        sQT[d*TPT + i] = Qb[e] * INVSC;
        sKl[i*PT + d] = g_Kland[bh*4096 + e];
        sW[e] = g_Wm[bh*4096 + e];
    }
    __syncthreads();

    // logits
    u64 pxp[4], pyp[4];
    #pragma unroll
    for (int p = 0; p < 4; p++) { pxp[p] = 0ull; pyp[p] = 0ull; }
    const float* cK0 = sKl + lane*PT;
    const float* cK1 = sKl + (lane+32)*PT;
    #pragma unroll 8
    for (int d = 0; d < 64; d++) {
        ulonglong2 a0 = *(const ulonglong2*)(sQT + d*TPT + r0);
        ulonglong2 a1 = *(const ulonglong2*)(sQT + d*TPT + r0 + 4);
        float b0 = cK0[d], b1 = cK1[d];
        u64 bb0 = pk2(b0, b0), bb1 = pk2(b1, b1);
        pxp[0] = fma2(a0.x, bb0, pxp[0]); pxp[1] = fma2(a0.y, bb0, pxp[1]);
        pxp[2] = fma2(a1.x, bb0, pxp[2]); pxp[3] = fma2(a1.y, bb0, pxp[3]);
        pyp[0] = fma2(a0.x, bb1, pyp[0]); pyp[1] = fma2(a0.y, bb1, pyp[1]);
        pyp[2] = fma2(a1.x, bb1, pyp[2]); pyp[3] = fma2(a1.y, bb1, pyp[3]);
    }
    float px[8], py[8];
    #pragma unroll
    for (int p = 0; p < 4; p++) {
        upk2(pxp[p], px[2*p], px[2*p+1]);
        upk2(pyp[p], py[2*p], py[2*p+1]);
    }
    #pragma unroll
    for (int r = 0; r < 8; r++) {
        const int i = r0 + r;
        float mx = warpMax(fmaxf(px[r], py[r]));
        float p0 = __expf(px[r] - mx), p1 = __expf(py[r] - mx);
        float s = warpSum(p0 + p1);
        float inv = 1.f / s;
        sPT[lane*TPT + i] = p0 * inv;
        sPT[(lane+32)*TPT + i] = p1 * inv;
    }
    __syncwarp();

    // PV
    u64 oxp[4], oyp[4];
    #pragma unroll
    for (int p = 0; p < 4; p++) { oxp[p] = 0ull; oyp[p] = 0ull; }
    #pragma unroll 8
    for (int j = 0; j < 64; j++) {
        ulonglong2 a0 = *(const ulonglong2*)(sPT + j*TPT + r0);
        ulonglong2 a1 = *(const ulonglong2*)(sPT + j*TPT + r0 + 4);
        float2 v = *(const float2*)(sW + j*64 + cc);
        u64 vx = pk2(v.x, v.x), vy = pk2(v.y, v.y);
        oxp[0] = fma2(a0.x, vx, oxp[0]); oxp[1] = fma2(a0.y, vx, oxp[1]);
        oxp[2] = fma2(a1.x, vx, oxp[2]); oxp[3] = fma2(a1.y, vx, oxp[3]);
        oyp[0] = fma2(a0.x, vy, oyp[0]); oyp[1] = fma2(a0.y, vy, oyp[1]);
        oyp[2] = fma2(a1.x, vy, oyp[2]); oyp[3] = fma2(a1.y, vy, oyp[3]);
    }
    float* Ob = out + ((size_t)bh*SEQ + tile*64)*HD;
    #pragma unroll
    for (int p = 0; p < 4; p++) {
        float f0x, f1x, f0y, f1y;
        upk2(oxp[p], f0x, f1x);
        upk2(oyp[p], f0y, f1y);
        const int i0 = r0 + 2*p;
        *(float2*)(Ob + i0*64 + cc)     = make_float2(f0x, f0y);
        *(float2*)(Ob + (i0+1)*64 + cc) = make_float2(f1x, f1y);
    }
}

// ---------------- launch ----------------
extern "C" void kernel_launch(void* const* d_in, const int* in_sizes, int n_in,
                              void* d_out, int out_size)
{
    const float* Q = (const float*)d_in[0];
    const float* K = (const float*)d_in[1];
    const float* V = (const float*)d_in[2];
    float* out = (float*)d_out;

    const int smLand  = (NL*HD + NL*PT + NL*NL + 8*64 + 128) * 4;
    const int smInv   = 5 * 4096 * 4;
    const int smChunk = (NL*TPT + NL*PT + NL*HD + NL*TPT) * 4;
    const int smComb  = (3*NSP*NL + 64 + 2*4096) * 4;
    const int smFinal = smChunk;

    cudaFuncSetAttribute(kLand,    cudaFuncAttributeMaxDynamicSharedMemorySize, smLand);
    cudaFuncSetAttribute(kInv,     cudaFuncAttributeMaxDynamicSharedMemorySize, smInv);
    cudaFuncSetAttribute(kChunk,   cudaFuncAttributeMaxDynamicSharedMemorySize, smChunk);
    cudaFuncSetAttribute(kCombine, cudaFuncAttributeMaxDynamicSharedMemorySize, smComb);
    cudaFuncSetAttribute(kFinal,   cudaFuncAttributeMaxDynamicSharedMemorySize, smFinal);

    kLand   <<<NBH, 256, smLand>>>(Q, K);
    kInv    <<<NBH, 256, smInv>>>();
    kChunk  <<<dim3(NSP, NBH), 256, smChunk>>>(K, V);
    kCombine<<<NBH, 256, smComb>>>();
    kFinal  <<<dim3(64, NBH), 256, smFinal>>>(Q, out);
}

// round 11
// speedup vs baseline: 1.0161x; 1.0161x over previous
#include <cuda_runtime.h>

#define SEQ   4096
#define HD    64
#define NL    64
#define NBH   48
#define NSP   16
#define CHUNK 256
#define PT    65
#define TPT   68
#define INVSC 0.35355339059327373f

typedef unsigned long long u64;

// ---------------- static scratch (no allocation) ----------------
__device__ float g_Qland[NBH*NL*HD];
__device__ float g_Kland[NBH*NL*HD];
__device__ float g_K2  [NBH*NL*NL];
__device__ float g_pinv[NBH*NL*NL];
__device__ float g_Wm  [NBH*NL*HD];
__device__ float g_Fp  [NBH*NSP*NL*HD];
__device__ float g_mp  [NBH*NSP*NL];
__device__ float g_sp  [NBH*NSP*NL];
__device__ float g_norms[2*NBH];

// ---------------- f32x2 packed helpers ----------------
__device__ __forceinline__ u64 pk2(float lo, float hi) {
    u64 r; asm("mov.b64 %0,{%1,%2};" : "=l"(r) : "f"(lo), "f"(hi)); return r;
}
__device__ __forceinline__ void upk2(u64 v, float& lo, float& hi) {
    asm("mov.b64 {%0,%1},%2;" : "=f"(lo), "=f"(hi) : "l"(v));
}
__device__ __forceinline__ u64 fma2(u64 a, u64 b, u64 c) {
    u64 d; asm("fma.rn.f32x2 %0,%1,%2,%3;" : "=l"(d) : "l"(a), "l"(b), "l"(c)); return d;
}
__device__ __forceinline__ u64 mul2(u64 a, u64 b) {
    u64 d; asm("mul.rn.f32x2 %0,%1,%2;" : "=l"(d) : "l"(a), "l"(b)); return d;
}

// ---------------- warp helpers ----------------
__device__ __forceinline__ float warpMax(float v) {
    #pragma unroll
    for (int o = 16; o > 0; o >>= 1) v = fmaxf(v, __shfl_xor_sync(0xffffffffu, v, o));
    return v;
}
__device__ __forceinline__ float warpSum(float v) {
    #pragma unroll
    for (int o = 16; o > 0; o >>= 1) v += __shfl_xor_sync(0xffffffffu, v, o);
    return v;
}

// C = alpha * A @ B, 64x64 pitch-64, 256 threads (scalar version for kInv/kCombine)
__device__ __forceinline__ void mm64(const float* __restrict__ A,
                                     const float* __restrict__ B,
                                     float* __restrict__ C,
                                     int tid, float alpha)
{
    const int w = tid >> 5, lane = tid & 31;
    const int r0 = w * 8, cc = lane * 2;
    float ax[8], ay[8];
    #pragma unroll
    for (int r = 0; r < 8; r++) { ax[r] = 0.f; ay[r] = 0.f; }
    #pragma unroll
    for (int k = 0; k < 64; k += 4) {
        float2 b0 = *(const float2*)(B + (k+0)*64 + cc);
        float2 b1 = *(const float2*)(B + (k+1)*64 + cc);
        float2 b2 = *(const float2*)(B + (k+2)*64 + cc);
        float2 b3 = *(const float2*)(B + (k+3)*64 + cc);
        #pragma unroll
        for (int r = 0; r < 8; r++) {
            float4 a = *(const float4*)(A + (r0+r)*64 + k);
            ax[r] += a.x*b0.x + a.y*b1.x + a.z*b2.x + a.w*b3.x;
            ay[r] += a.x*b0.y + a.y*b1.y + a.z*b2.y + a.w*b3.y;
        }
    }
    #pragma unroll
    for (int r = 0; r < 8; r++)
        *(float2*)(C + (r0+r)*64 + cc) = make_float2(alpha*ax[r], alpha*ay[r]);
}

// ---------------- phase 1: landmarks + kernel_2 + norms ----------------
__global__ void kLand(const float* __restrict__ Q, const float* __restrict__ K)
{
    extern __shared__ float sm[];
    float* sQl  = sm;
    float* sKl  = sQl + NL*HD;
    float* sL   = sKl + NL*PT;
    float* sCol = sL  + NL*NL;
    float* sRed = sCol + 8*64;

    const int bh = blockIdx.x, tid = threadIdx.x;
    const float* Qb = Q + (size_t)bh*SEQ*HD;
    const float* Kb = K + (size_t)bh*SEQ*HD;
    const float cs = INVSC * (1.0f/64.0f);

    // pooling with float4 loads: 8x fewer LDG, much better MLP
    for (int e4 = tid; e4 < NL*HD/4; e4 += 256) {
        int l = e4 >> 4, d4 = (e4 & 15) << 2;
        const float4* qp = (const float4*)(Qb + (size_t)(l*64)*HD + d4);
        const float4* kp = (const float4*)(Kb + (size_t)(l*64)*HD + d4);
        float4 aq = make_float4(0.f,0.f,0.f,0.f);
        float4 ak = make_float4(0.f,0.f,0.f,0.f);
        #pragma unroll 8
        for (int r = 0; r < 64; r++) {
            float4 q = qp[r*16];
            float4 k2 = kp[r*16];
            aq.x += q.x; aq.y += q.y; aq.z += q.z; aq.w += q.w;
            ak.x += k2.x; ak.y += k2.y; ak.z += k2.z; ak.w += k2.w;
        }
        aq.x *= cs; aq.y *= cs; aq.z *= cs; aq.w *= cs;
        ak.x *= cs; ak.y *= cs; ak.z *= cs; ak.w *= cs;
        *(float4*)(sQl + l*64 + d4) = aq;
        sKl[l*PT + d4+0] = ak.x; sKl[l*PT + d4+1] = ak.y;
        sKl[l*PT + d4+2] = ak.z; sKl[l*PT + d4+3] = ak.w;
        *(float4*)(g_Qland + bh*NL*HD + l*64 + d4) = aq;
        *(float4*)(g_Kland + bh*NL*HD + l*64 + d4) = ak;
    }
    __syncthreads();

    const int w = tid >> 5, lane = tid & 31;
    const int r0 = w * 8;

    float px[8], py[8];
    #pragma unroll
    for (int r = 0; r < 8; r++) { px[r] = 0.f; py[r] = 0.f; }
    #pragma unroll
    for (int k = 0; k < 64; k += 4) {
        const float* bp0 = sKl + lane*PT + k;
        const float* bp1 = sKl + (lane+32)*PT + k;
        float b00 = bp0[0], b01 = bp0[1], b02 = bp0[2], b03 = bp0[3];
        float b10 = bp1[0], b11 = bp1[1], b12 = bp1[2], b13 = bp1[3];
        #pragma unroll
        for (int r = 0; r < 8; r++) {
            float4 a = *(const float4*)(sQl + (r0+r)*64 + k);
            px[r] += a.x*b00 + a.y*b01 + a.z*b02 + a.w*b03;
            py[r] += a.x*b10 + a.y*b11 + a.z*b12 + a.w*b13;
        }
    }

    float cs0 = 0.f, cs1 = 0.f;
    #pragma unroll
    for (int r = 0; r < 8; r++) {
        const int i = r0 + r;
        float mx = warpMax(fmaxf(px[r], py[r]));
        float p0 = __expf(px[r] - mx), p1 = __expf(py[r] - mx);
        float s = warpSum(p0 + p1);
        float inv = 1.f / s;
        p0 *= inv; p1 *= inv;
        sL[i*64 + lane] = p0;
        sL[i*64 + lane + 32] = p1;
        cs0 += p0; cs1 += p1;
        float rs = warpSum(p0 + p1);
        if (lane == 0) sRed[i] = rs;
    }
    sCol[w*64 + lane] = cs0;
    sCol[w*64 + lane + 32] = cs1;
    __syncthreads();

    for (int e = tid; e < NL*NL; e += 256) g_K2[bh*NL*NL + e] = sL[e];
    if (tid < 64) {
        float t = 0.f;
        #pragma unroll
        for (int ww = 0; ww < 8; ww++) t += sCol[ww*64 + tid];
        sRed[64 + tid] = t;
    }
    __syncthreads();
    if (tid == 0) {
        float rm = 0.f, cm = 0.f;
        for (int t = 0; t < 64; t++) {
            rm = fmaxf(rm, sRed[t]);
            cm = fmaxf(cm, sRed[64 + t]);
        }
        g_norms[bh] = rm;
        g_norms[NBH + bh] = cm;
    }
}

// ---------------- phase 2: Newton-Schulz pseudo-inverse ----------------
__global__ void kInv()
{
    extern __shared__ float sm[];
    float* bK = sm;
    float* bA = sm + 4096;
    float* bT = sm + 2*4096;
    float* bV = sm + 3*4096;
    float* bU = sm + 4*4096;
    const int bh = blockIdx.x, tid = threadIdx.x;

    for (int e = tid; e < 4096; e += 256) bK[e] = g_K2[bh*4096 + e];
    __syncthreads();
    float rm = 0.f, cm = 0.f;
    #pragma unroll
    for (int i = 0; i < NBH; i++) {
        rm = fmaxf(rm, g_norms[i]);
        cm = fmaxf(cm, g_norms[NBH + i]);
    }
    const float sc = 1.f / (rm * cm);
    for (int e = tid; e < 4096; e += 256) {
        int i = e >> 6, j = e & 63;
        bV[e] = sc * bK[j*64 + i];
    }
    __syncthreads();

    for (int it = 0; it < 6; it++) {
        mm64(bK, bV, bA, tid, 1.f); __syncthreads();
        for (int e = tid; e < 4096; e += 256)
            bT[e] = (((e>>6) == (e&63)) ? 7.f : 0.f) - bA[e];
        __syncthreads();
        mm64(bA, bT, bU, tid, 1.f); __syncthreads();
        for (int e = tid; e < 4096; e += 256)
            bT[e] = (((e>>6) == (e&63)) ? 15.f : 0.f) - bU[e];
        __syncthreads();
        mm64(bA, bT, bU, tid, 1.f); __syncthreads();
        for (int e = tid; e < 4096; e += 256)
            bT[e] = (((e>>6) == (e&63)) ? 13.f : 0.f) - bU[e];
        __syncthreads();
        mm64(bV, bT, bU, tid, 0.25f); __syncthreads();
        float* t = bV; bV = bU; bU = t;
    }
    for (int e = tid; e < 4096; e += 256) g_pinv[bh*4096 + e] = bV[e];
}

// ---------------- phase 4: kernel_3 @ V with split online softmax (f32x2) ----------------
// smem: sQlT[64*TPT] sK[64*PT] sV[64*64] sPT[64*TPT]
__global__ void __launch_bounds__(256, 3)
kChunk(const float* __restrict__ K, const float* __restrict__ V)
{
    extern __shared__ float sm[];
    float* sQlT = sm;
    float* sK   = sQlT + NL*TPT;
    float* sV   = sK   + NL*PT;
    float* sPT  = sV   + NL*HD;

    const int bh = blockIdx.y, sp = blockIdx.x, tid = threadIdx.x;
    const int w = tid >> 5, lane = tid & 31;
    const int r0 = w * 8, cc = lane * 2;

    // transposed landmark-Q tile (coalesced gmem read; 4-way smem write conflict, once)
    for (int e = tid; e < 4096; e += 256) {
        int i = e >> 6, d = e & 63;
        sQlT[d*TPT + i] = g_Qland[bh*4096 + e];
    }

    u64 fxp[4], fyp[4];
    float mrun[8], srun[8];
    #pragma unroll
    for (int p = 0; p < 4; p++) { fxp[p] = 0ull; fyp[p] = 0ull; }
    #pragma unroll
    for (int r = 0; r < 8; r++) { mrun[r] = -1e30f; srun[r] = 0.f; }

    for (int t = 0; t < 4; t++) {
        __syncthreads();
        const size_t rowBase = (size_t)bh*SEQ + sp*CHUNK + t*64;
        const float* Kb = K + rowBase*HD;
        const float* Vb = V + rowBase*HD;
        for (int e = tid; e < NL*HD; e += 256) {
            int j = e >> 6, d = e & 63;
            sK[j*PT + d] = Kb[e] * INVSC;
            sV[e] = Vb[e];
        }
        __syncthreads();

        // logits: row-pair packed f32x2
        u64 pxp[4], pyp[4];
        #pragma unroll
        for (int p = 0; p < 4; p++) { pxp[p] = 0ull; pyp[p] = 0ull; }
        const float* cK0 = sK + lane*PT;
        const float* cK1 = sK + (lane+32)*PT;
        #pragma unroll 8
        for (int d = 0; d < 64; d++) {
            ulonglong2 a0 = *(const ulonglong2*)(sQlT + d*TPT + r0);
            ulonglong2 a1 = *(const ulonglong2*)(sQlT + d*TPT + r0 + 4);
            float b0 = cK0[d], b1 = cK1[d];
            u64 bb0 = pk2(b0, b0), bb1 = pk2(b1, b1);
            pxp[0] = fma2(a0.x, bb0, pxp[0]); pxp[1] = fma2(a0.y, bb0, pxp[1]);
            pxp[2] = fma2(a1.x, bb0, pxp[2]); pxp[3] = fma2(a1.y, bb0, pxp[3]);
            pyp[0] = fma2(a0.x, bb1, pyp[0]); pyp[1] = fma2(a0.y, bb1, pyp[1]);
            pyp[2] = fma2(a1.x, bb1, pyp[2]); pyp[3] = fma2(a1.y, bb1, pyp[3]);
        }
        float px[8], py[8];
        #pragma unroll
        for (int p = 0; p < 4; p++) {
            upk2(pxp[p], px[2*p], px[2*p+1]);
            upk2(pyp[p], py[2*p], py[2*p+1]);
        }

        float al[8];
        #pragma unroll
        for (int r = 0; r < 8; r++) {
            const int i = r0 + r;
            float tmax = warpMax(fmaxf(px[r], py[r]));
            float nm = fmaxf(mrun[r], tmax);
            al[r] = __expf(mrun[r] - nm);
            float p0 = __expf(px[r] - nm), p1 = __expf(py[r] - nm);
            srun[r] = srun[r]*al[r] + warpSum(p0 + p1);
            mrun[r] = nm;
            sPT[lane*TPT + i] = p0;
            sPT[(lane+32)*TPT + i] = p1;
        }
        __syncwarp();   // P rows are warp-private in sPT -> no block barrier needed

        #pragma unroll
        for (int p = 0; p < 4; p++) {
            u64 alp = pk2(al[2*p], al[2*p+1]);
            fxp[p] = mul2(fxp[p], alp);
            fyp[p] = mul2(fyp[p], alp);
        }

        // PV: row-pair packed f32x2
        #pragma unroll 8
        for (int j = 0; j < 64; j++) {
            ulonglong2 a0 = *(const ulonglong2*)(sPT + j*TPT + r0);
            ulonglong2 a1 = *(const ulonglong2*)(sPT + j*TPT + r0 + 4);
            float2 v = *(const float2*)(sV + j*64 + cc);
            u64 vx = pk2(v.x, v.x), vy = pk2(v.y, v.y);
            fxp[0] = fma2(a0.x, vx, fxp[0]); fxp[1] = fma2(a0.y, vx, fxp[1]);
            fxp[2] = fma2(a1.x, vx, fxp[2]); fxp[3] = fma2(a1.y, vx, fxp[3]);
            fyp[0] = fma2(a0.x, vy, fyp[0]); fyp[1] = fma2(a0.y, vy, fyp[1]);
            fyp[2] = fma2(a1.x, vy, fyp[2]); fyp[3] = fma2(a1.y, vy, fyp[3]);
        }
    }

    const size_t base = (size_t)bh*NSP + sp;
    #pragma unroll
    for (int r = 0; r < 8; r++) {
        if (lane == 0) {
            g_mp[base*64 + r0 + r] = mrun[r];
            g_sp[base*64 + r0 + r] = srun[r];
        }
    }
    #pragma unroll
    for (int p = 0; p < 4; p++) {
        float f0x, f1x, f0y, f1y;
        upk2(fxp[p], f0x, f1x);
        upk2(fyp[p], f0y, f1y);
        const int i0 = r0 + 2*p;
        *(float2*)(g_Fp + base*4096 + i0*64 + cc)     = make_float2(f0x, f0y);
        *(float2*)(g_Fp + base*4096 + (i0+1)*64 + cc) = make_float2(f1x, f1y);
    }
}

// ---------------- phase 5: combine split partials + W = pinv @ F ----------------
__global__ void kCombine()
{
    extern __shared__ float sm[];
    float* sMs  = sm;
    float* sSs  = sMs + NSP*NL;
    float* sWt  = sSs + NSP*NL;
    float* sInv = sWt + NSP*NL;
    float* sF   = sInv + 64;
    float* sPinv = sF + 4096;

    const int bh = blockIdx.x, tid = threadIdx.x;
    for (int e = tid; e < NSP*NL; e += 256) {
        sMs[e] = g_mp[bh*NSP*NL + e];
        sSs[e] = g_sp[bh*NSP*NL + e];
    }
    __syncthreads();
    if (tid < 64) {
        float M = -1e30f;
        #pragma unroll
        for (int sp = 0; sp < NSP; sp++) M = fmaxf(M, sMs[sp*64 + tid]);
        float S = 0.f;
        #pragma unroll
        for (int sp = 0; sp < NSP; sp++) {
            float wgt = __expf(sMs[sp*64 + tid] - M);
            sWt[sp*64 + tid] = wgt;
            S += wgt * sSs[sp*64 + tid];
        }
        sInv[tid] = 1.f / S;
    }
    __syncthreads();
    // float4 partial reduction over the 16 splits (LDG.128, high MLP)
    for (int e4 = tid; e4 < 1024; e4 += 256) {
        const int i = e4 >> 4;
        float4 acc = make_float4(0.f,0.f,0.f,0.f);
        #pragma unroll
        for (int sp = 0; sp < NSP; sp++) {
            float4 v = *(const float4*)(g_Fp + ((size_t)bh*NSP + sp)*4096 + e4*4);
            float wgt = sWt[sp*64 + i];
            acc.x += wgt*v.x; acc.y += wgt*v.y; acc.z += wgt*v.z; acc.w += wgt*v.w;
        }
        float inv = sInv[i];
        *(float4*)(sF + e4*4) = make_float4(acc.x*inv, acc.y*inv, acc.z*inv, acc.w*inv);
    }
    for (int e4 = tid; e4 < 1024; e4 += 256)
        *(float4*)(sPinv + e4*4) = *(const float4*)(g_pinv + bh*4096 + e4*4);
    __syncthreads();
    mm64(sPinv, sF, g_Wm + bh*4096, tid, 1.f);
}

// ---------------- phase 6: out = softmax(Q @ Kland^T) @ W (f32x2) ----------------
// smem: sQT[64*TPT] sKl[64*PT] sPT[64*TPT] sW[64*64]
__global__ void __launch_bounds__(256, 3)
kFinal(const float* __restrict__ Q, float* __restrict__ out)
{
    extern __shared__ float sm[];
    float* sQT = sm;
    float* sKl = sQT + NL*TPT;
    float* sPT = sKl + NL*PT;
    float* sW  = sPT + NL*TPT;

    const int bh = blockIdx.y, tile = blockIdx.x, tid = threadIdx.x;
    const int w = tid >> 5, lane = tid & 31;
    const int r0 = w * 8, cc = lane * 2;

    const float* Qb = Q + ((size_t)bh*SEQ + tile*64)*HD;
    for (int e = tid; e < 4096; e += 256) {
        int i = e >> 6, d = e & 63;
        sQT[d*TPT + i] = Qb[e] * INVSC;
        sKl[i*PT + d] = g_Kland[bh*4096 + e];
        sW[e] = g_Wm[bh*4096 + e];
    }
    __syncthreads();

    // logits
    u64 pxp[4], pyp[4];
    #pragma unroll
    for (int p = 0; p < 4; p++) { pxp[p] = 0ull; pyp[p] = 0ull; }
    const float* cK0 = sKl + lane*PT;
    const float* cK1 = sKl + (lane+32)*PT;
    #pragma unroll 8
    for (int d = 0; d < 64; d++) {
        ulonglong2 a0 = *(const ulonglong2*)(sQT + d*TPT + r0);
        ulonglong2 a1 = *(const ulonglong2*)(sQT + d*TPT + r0 + 4);
        float b0 = cK0[d], b1 = cK1[d];
        u64 bb0 = pk2(b0, b0), bb1 = pk2(b1, b1);
        pxp[0] = fma2(a0.x, bb0, pxp[0]); pxp[1] = fma2(a0.y, bb0, pxp[1]);
        pxp[2] = fma2(a1.x, bb0, pxp[2]); pxp[3] = fma2(a1.y, bb0, pxp[3]);
        pyp[0] = fma2(a0.x, bb1, pyp[0]); pyp[1] = fma2(a0.y, bb1, pyp[1]);
        pyp[2] = fma2(a1.x, bb1, pyp[2]); pyp[3] = fma2(a1.y, bb1, pyp[3]);
    }
    float px[8], py[8];
    #pragma unroll
    for (int p = 0; p < 4; p++) {
        upk2(pxp[p], px[2*p], px[2*p+1]);
        upk2(pyp[p], py[2*p], py[2*p+1]);
    }
    #pragma unroll
    for (int r = 0; r < 8; r++) {
        const int i = r0 + r;
        float mx = warpMax(fmaxf(px[r], py[r]));
        float p0 = __expf(px[r] - mx), p1 = __expf(py[r] - mx);
        float s = warpSum(p0 + p1);
        float inv = 1.f / s;
        sPT[lane*TPT + i] = p0 * inv;
        sPT[(lane+32)*TPT + i] = p1 * inv;
    }
    __syncwarp();

    // PV
    u64 oxp[4], oyp[4];
    #pragma unroll
    for (int p = 0; p < 4; p++) { oxp[p] = 0ull; oyp[p] = 0ull; }
    #pragma unroll 8
    for (int j = 0; j < 64; j++) {
        ulonglong2 a0 = *(const ulonglong2*)(sPT + j*TPT + r0);
        ulonglong2 a1 = *(const ulonglong2*)(sPT + j*TPT + r0 + 4);
        float2 v = *(const float2*)(sW + j*64 + cc);
        u64 vx = pk2(v.x, v.x), vy = pk2(v.y, v.y);
        oxp[0] = fma2(a0.x, vx, oxp[0]); oxp[1] = fma2(a0.y, vx, oxp[1]);
        oxp[2] = fma2(a1.x, vx, oxp[2]); oxp[3] = fma2(a1.y, vx, oxp[3]);
        oyp[0] = fma2(a0.x, vy, oyp[0]); oyp[1] = fma2(a0.y, vy, oyp[1]);
        oyp[2] = fma2(a1.x, vy, oyp[2]); oyp[3] = fma2(a1.y, vy, oyp[3]);
    }
    float* Ob = out + ((size_t)bh*SEQ + tile*64)*HD;
    #pragma unroll
    for (int p = 0; p < 4; p++) {
        float f0x, f1x, f0y, f1y;
        upk2(oxp[p], f0x, f1x);
        upk2(oyp[p], f0y, f1y);
        const int i0 = r0 + 2*p;
        *(float2*)(Ob + i0*64 + cc)     = make_float2(f0x, f0y);
        *(float2*)(Ob + (i0+1)*64 + cc) = make_float2(f1x, f1y);
    }
}

// ---------------- launch ----------------
extern "C" void kernel_launch(void* const* d_in, const int* in_sizes, int n_in,
                              void* d_out, int out_size)
{
    const float* Q = (const float*)d_in[0];
    const float* K = (const float*)d_in[1];
    const float* V = (const float*)d_in[2];
    float* out = (float*)d_out;

    const int smLand  = (NL*HD + NL*PT + NL*NL + 8*64 + 128) * 4;
    const int smInv   = 5 * 4096 * 4;
    const int smChunk = (NL*TPT + NL*PT + NL*HD + NL*TPT) * 4;
    const int smComb  = (3*NSP*NL + 64 + 2*4096) * 4;
    const int smFinal = smChunk;

    cudaFuncSetAttribute(kLand,    cudaFuncAttributeMaxDynamicSharedMemorySize, smLand);
    cudaFuncSetAttribute(kInv,     cudaFuncAttributeMaxDynamicSharedMemorySize, smInv);
    cudaFuncSetAttribute(kChunk,   cudaFuncAttributeMaxDynamicSharedMemorySize, smChunk);
    cudaFuncSetAttribute(kCombine, cudaFuncAttributeMaxDynamicSharedMemorySize, smComb);
    cudaFuncSetAttribute(kFinal,   cudaFuncAttributeMaxDynamicSharedMemorySize, smFinal);

    kLand   <<<NBH, 256, smLand>>>(Q, K);
    kInv    <<<NBH, 256, smInv>>>();
    kChunk  <<<dim3(NSP, NBH), 256, smChunk>>>(K, V);
    kCombine<<<NBH, 256, smComb>>>();
    kFinal  <<<dim3(64, NBH), 256, smFinal>>>(Q, out);
}